// round 14
// baseline (speedup 1.0000x reference)
#include <cuda_runtime.h>
#include <cuda_bf16.h>

#define N_NODES  100000
#define N_EDGES  1600000
#define N_FEAT   32
#define HIDDEN   128
#define N_GRAPHS 256

#define SCAN_T   1024
#define SCAN_NB  98          // ceil(100000/1024)

#define UBM 128              // update kernel M-tile (nodes per block)
#define NPAD (N_NODES + UBM) // zero-padded rows for tail block

// ---------------- scratch (static device globals; no allocation) ----------------
__device__ float         g_h [NPAD * HIDDEN];   // fp32 h, natural layout (aggregate gathers this)
__device__ __nv_bfloat16 g_hh[NPAD * HIDDEN];   // h hi (bf16)
__device__ __nv_bfloat16 g_hl[NPAD * HIDDEN];   // h lo (bf16)
__device__ __nv_bfloat16 g_ah[NPAD * HIDDEN];   // agg hi
__device__ __nv_bfloat16 g_al[NPAD * HIDDEN];   // agg lo
__device__ uint2 g_wfrag[16 * 16 * 2 * 32];     // [cc][j][hi/lo][lane] b-fragments, 128KB
__device__ int   g_degi[N_NODES];
__device__ int   g_rowptr[N_NODES + 1];
__device__ int   g_cursor[N_NODES];
__device__ int   g_ssrc[N_EDGES];               // 6.4 MB
__device__ int   g_bsum[SCAN_NB];
__device__ float g_cnt[N_GRAPHS];
__device__ float g_pool[N_GRAPHS * HIDDEN];

// ---------------- helpers ----------------
__device__ __forceinline__ void red_add_v4(float* addr, float4 v) {
    asm volatile("red.global.add.v4.f32 [%0], {%1, %2, %3, %4};"
                 :: "l"(addr), "f"(v.x), "f"(v.y), "f"(v.z), "f"(v.w)
                 : "memory");
}

__device__ __forceinline__ unsigned pack_bf2(__nv_bfloat16 a, __nv_bfloat16 b) {
    __nv_bfloat162 t;
    t.x = a; t.y = b;
    return *reinterpret_cast<unsigned*>(&t);
}

__device__ __forceinline__ void split_bf(float v, __nv_bfloat16& hi, __nv_bfloat16& lo) {
    hi = __float2bfloat16(v);
    lo = __float2bfloat16(v - __bfloat162float(hi));
}

__device__ __forceinline__ void mma16816(float* d, const unsigned* a, unsigned b0, unsigned b1) {
    asm volatile(
        "mma.sync.aligned.m16n8k16.row.col.f32.bf16.bf16.f32 "
        "{%0,%1,%2,%3}, {%4,%5,%6,%7}, {%8,%9}, {%0,%1,%2,%3};\n"
        : "+f"(d[0]), "+f"(d[1]), "+f"(d[2]), "+f"(d[3])
        : "r"(a[0]), "r"(a[1]), "r"(a[2]), "r"(a[3]), "r"(b0), "r"(b1));
}

// ---------------- zero: degi, cnt, pool ----------------
__global__ void zero_kernel(int* __restrict__ degi, float* __restrict__ cnt,
                            float* __restrict__ pool)
{
    int i = blockIdx.x * blockDim.x + threadIdx.x;
    int stride = gridDim.x * blockDim.x;
    for (int j = i; j < N_NODES; j += stride) degi[j] = 0;
    for (int j = i; j < N_GRAPHS * HIDDEN; j += stride) pool[j] = 0.f;
    if (i < N_GRAPHS) cnt[i] = 0.f;
}

// ---------------- weight pre-split into b-fragment layout ----------------
__global__ void wsplit_kernel(const float* __restrict__ Wl, const float* __restrict__ Wr,
                              uint2* __restrict__ wfrag)
{
    int idx = blockIdx.x * 256 + threadIdx.x;      // 0..16383
    int lane = idx & 31;
    int p    = (idx >> 5) & 1;
    int j    = (idx >> 6) & 15;
    int cc   = idx >> 10;
    int gq = lane >> 2, tg = lane & 3;
    int n  = j * 8 + gq;
    int kb = cc * 16 + 2 * tg;

    int ks[4] = {kb, kb + 1, kb + 8, kb + 9};
    __nv_bfloat16 b[4];
#pragma unroll
    for (int i = 0; i < 4; i++) {
        int k = ks[i];
        float v = (k < 128) ? Wl[k * HIDDEN + n] : Wr[(k - 128) * HIDDEN + n];
        __nv_bfloat16 hi, lo;
        split_bf(v, hi, lo);
        b[i] = p ? lo : hi;
    }
    wfrag[idx] = make_uint2(pack_bf2(b[0], b[1]), pack_bf2(b[2], b[3]));
}

// ---------------- fused: proj (h = x @ W_op + b_op, + bf16 split) + hist + count ----------------
#define PROJ_NPB 64
__global__ __launch_bounds__(128) void proj_hist_kernel(
    const float* __restrict__ x, const float* __restrict__ W,
    const float* __restrict__ b, float* __restrict__ h,
    __nv_bfloat16* __restrict__ hh, __nv_bfloat16* __restrict__ hl,
    const int* __restrict__ dst, int* __restrict__ degi,
    const int* __restrict__ batch, float* __restrict__ cnt)
{
    __shared__ __align__(16) float xs[PROJ_NPB][N_FEAT];  // 8 KB
    int j = threadIdx.x;
    int base = blockIdx.x * PROJ_NPB;

    float w[N_FEAT];
#pragma unroll
    for (int k = 0; k < N_FEAT; k++) w[k] = W[k * HIDDEN + j];
    float bj = b[j];

    for (int i = j; i < PROJ_NPB * N_FEAT; i += 128) {
        int m = i / N_FEAT, c = i % N_FEAT;
        int node = base + m;
        xs[m][c] = (node < N_NODES) ? x[(long long)node * N_FEAT + c] : 0.f;
    }
    __syncthreads();

    for (int m = 0; m < PROJ_NPB; m++) {
        int node = base + m;
        if (node >= N_NODES) break;
        float acc = bj;
#pragma unroll
        for (int k = 0; k < N_FEAT; k++) acc += xs[m][k] * w[k];
        long long ofs = (long long)node * HIDDEN + j;
        h[ofs] = acc;
        __nv_bfloat16 hi, lo;
        split_bf(acc, hi, lo);
        hh[ofs] = hi;
        hl[ofs] = lo;
    }

    // histogram + batch count (grid-stride, independent of proj output)
    int gt = blockIdx.x * 128 + threadIdx.x;
    int stride = gridDim.x * 128;
    for (int e = gt; e < N_EDGES; e += stride) atomicAdd(&degi[dst[e]], 1);
    for (int i2 = gt; i2 < N_NODES; i2 += stride) atomicAdd(&cnt[batch[i2]], 1.0f);
}

// ---------------- hierarchical scan: degi -> rowptr (exclusive) ----------------
__global__ __launch_bounds__(SCAN_T) void scan_local(
    const int* __restrict__ degi, int* __restrict__ rowptr, int* __restrict__ bsum)
{
    __shared__ int sm[SCAN_T];
    int t = threadIdx.x;
    int i = blockIdx.x * SCAN_T + t;
    int v = (i < N_NODES) ? degi[i] : 0;
    sm[t] = v;
    __syncthreads();
#pragma unroll
    for (int off = 1; off < SCAN_T; off <<= 1) {
        int add = (t >= off) ? sm[t - off] : 0;
        __syncthreads();
        sm[t] += add;
        __syncthreads();
    }
    if (i < N_NODES) rowptr[i] = sm[t] - v;
    if (t == SCAN_T - 1) bsum[blockIdx.x] = sm[t];
}

__global__ void scan_bsum(int* __restrict__ bsum) {
    if (threadIdx.x == 0) {
        int acc = 0;
        for (int b = 0; b < SCAN_NB; b++) { int v = bsum[b]; bsum[b] = acc; acc += v; }
    }
}

__global__ void scan_add(int* __restrict__ rowptr, const int* __restrict__ bsum,
                         int* __restrict__ cursor)
{
    int i = blockIdx.x * blockDim.x + threadIdx.x;
    if (i < N_NODES) {
        int v = rowptr[i] + bsum[i / SCAN_T];
        rowptr[i] = v;
        cursor[i] = v;
    }
    if (i == 0) rowptr[N_NODES] = N_EDGES;
}

// ---------------- bucket edges by dst (full parallelism) ----------------
__global__ void bucket_kernel(const int* __restrict__ src, const int* __restrict__ dst,
                              int* __restrict__ cursor, int* __restrict__ ssrc)
{
    int i = blockIdx.x * blockDim.x + threadIdx.x;
    if (i < N_EDGES) {
        int d = dst[i];
        int pos = atomicAdd(&cursor[d], 1);
        ssrc[pos] = src[i];
    }
}

// ---------------- CSR aggregate: agg[n] = mean of h[neighbors(n)] -> bf16 hi/lo ----------------
__global__ __launch_bounds__(256) void aggregate_kernel(
    const int* __restrict__ rowptr, const int* __restrict__ ssrc,
    const float* __restrict__ h,
    __nv_bfloat16* __restrict__ ah, __nv_bfloat16* __restrict__ al)
{
    int node = blockIdx.x * 8 + (threadIdx.x >> 5);
    if (node >= N_NODES) return;
    int lane = threadIdx.x & 31;
    int beg = __ldg(&rowptr[node]);
    int end = __ldg(&rowptr[node + 1]);

    float4 acc = make_float4(0.f, 0.f, 0.f, 0.f);
    int e = beg;
    for (; e + 4 <= end; e += 4) {
        int s0 = __ldg(&ssrc[e + 0]);
        int s1 = __ldg(&ssrc[e + 1]);
        int s2 = __ldg(&ssrc[e + 2]);
        int s3 = __ldg(&ssrc[e + 3]);
        float4 v0 = *(const float4*)(h + (long long)s0 * HIDDEN + lane * 4);
        float4 v1 = *(const float4*)(h + (long long)s1 * HIDDEN + lane * 4);
        float4 v2 = *(const float4*)(h + (long long)s2 * HIDDEN + lane * 4);
        float4 v3 = *(const float4*)(h + (long long)s3 * HIDDEN + lane * 4);
        acc.x += (v0.x + v1.x) + (v2.x + v3.x);
        acc.y += (v0.y + v1.y) + (v2.y + v3.y);
        acc.z += (v0.z + v1.z) + (v2.z + v3.z);
        acc.w += (v0.w + v1.w) + (v2.w + v3.w);
    }
    for (; e < end; e++) {
        int s0 = __ldg(&ssrc[e]);
        float4 v0 = *(const float4*)(h + (long long)s0 * HIDDEN + lane * 4);
        acc.x += v0.x; acc.y += v0.y; acc.z += v0.z; acc.w += v0.w;
    }
    float invd = 1.0f / fmaxf((float)(end - beg), 1.0f);
    acc.x *= invd; acc.y *= invd; acc.z *= invd; acc.w *= invd;

    __nv_bfloat16 h0, l0, h1, l1, h2, l2, h3, l3;
    split_bf(acc.x, h0, l0);
    split_bf(acc.y, h1, l1);
    split_bf(acc.z, h2, l2);
    split_bf(acc.w, h3, l3);
    long long ofs = (long long)node * HIDDEN + lane * 4;
    *(uint2*)(ah + ofs) = make_uint2(pack_bf2(h0, h1), pack_bf2(h2, h3));
    *(uint2*)(al + ofs) = make_uint2(pack_bf2(l0, l1), pack_bf2(l2, l3));
}

// ---------------- tensor-core update: h = LN(elu([agg|h] @ [Wl;Wr] + bl)) ----------------
// 128 nodes x 128 cols per block, 256 threads (8 warps: 4 along M x 2 along N),
// each warp owns TWO 16-row m-tiles. 2 blocks/SM via launch_bounds(256,2).
// a-frag loads are register double-buffered: chunk c+1's 16 LDGs issue BEFORE
// chunk c's 48 MMAs, hiding the L2 latency behind the MMA chain.
__global__ __launch_bounds__(256, 2) void update_mma_kernel(
    const __nv_bfloat16* __restrict__ Aggh, const __nv_bfloat16* __restrict__ Aggl,
    __nv_bfloat16* __restrict__ Hh, __nv_bfloat16* __restrict__ Hl,
    float* __restrict__ h, const uint2* __restrict__ wfrag,
    const float* __restrict__ bl, const float* __restrict__ gamma,
    const float* __restrict__ beta, const int* __restrict__ batch,
    float* __restrict__ pooled, int do_pool)
{
    __shared__ float C[64][132];                  // epilogue staging, one 64-row half at a time

    int tid  = threadIdx.x;
    int lane = tid & 31;
    int w    = tid >> 5;
    int wm = w & 3, wn = w >> 2;
    int mbase = wm * 16, nbase = wn * 64;
    int base = blockIdx.x * UBM;
    int gq = lane >> 2, tg = lane & 3;

    // 32-bit offsets (arrays are < 2^31 elements) to save registers
    unsigned rA = (unsigned)(base + mbase + gq) * HIDDEN;   // tile0 row 0
    unsigned rB = rA + 8 * HIDDEN;                          // tile0 row +8
    unsigned rC = rA + 64 * HIDDEN;                         // tile1 row 0
    unsigned rD = rA + 72 * HIDDEN;                         // tile1 row +8

    float acc[2][8][4];
#pragma unroll
    for (int t2 = 0; t2 < 2; t2++)
#pragma unroll
        for (int j = 0; j < 8; j++)
#pragma unroll
            for (int i = 0; i < 4; i++) acc[t2][j][i] = 0.f;

    // a-frag chunk loader: a[0..3]=tile0 hi, a[4..7]=tile1 hi, a[8..11]=tile0 lo, a[12..15]=tile1 lo
    auto load_achunk = [&](const __nv_bfloat16* PH, const __nv_bfloat16* PL,
                           unsigned kk, unsigned* a) {
        a[0]  = *(const unsigned*)(PH + rA + kk);
        a[1]  = *(const unsigned*)(PH + rB + kk);
        a[2]  = *(const unsigned*)(PH + rA + kk + 8);
        a[3]  = *(const unsigned*)(PH + rB + kk + 8);
        a[4]  = *(const unsigned*)(PH + rC + kk);
        a[5]  = *(const unsigned*)(PH + rD + kk);
        a[6]  = *(const unsigned*)(PH + rC + kk + 8);
        a[7]  = *(const unsigned*)(PH + rD + kk + 8);
        a[8]  = *(const unsigned*)(PL + rA + kk);
        a[9]  = *(const unsigned*)(PL + rB + kk);
        a[10] = *(const unsigned*)(PL + rA + kk + 8);
        a[11] = *(const unsigned*)(PL + rB + kk + 8);
        a[12] = *(const unsigned*)(PL + rC + kk);
        a[13] = *(const unsigned*)(PL + rD + kk);
        a[14] = *(const unsigned*)(PL + rC + kk + 8);
        a[15] = *(const unsigned*)(PL + rD + kk + 8);
    };

    auto mma_chunk = [&](const unsigned* a, int ccg) {
        const uint2* wf = wfrag + (ccg * 16 + wn * 8) * 2 * 32 + lane;
#pragma unroll
        for (int jj = 0; jj < 8; jj++) {
            uint2 bh = __ldg(wf + (jj * 2) * 32);
            uint2 bb = __ldg(wf + (jj * 2 + 1) * 32);
            mma16816(acc[0][jj], a,      bh.x, bh.y);
            mma16816(acc[0][jj], a,      bb.x, bb.y);
            mma16816(acc[0][jj], a + 8,  bh.x, bh.y);
            mma16816(acc[1][jj], a + 4,  bh.x, bh.y);
            mma16816(acc[1][jj], a + 4,  bb.x, bb.y);
            mma16816(acc[1][jj], a + 12, bh.x, bh.y);
        }
    };

    unsigned bufA[16], bufB[16];
    unsigned kbase = 2 * tg;

    // ---- group 0: agg half (global chunks 0..7) ----
    load_achunk(Aggh, Aggl, kbase, bufA);
#pragma unroll 1
    for (int c = 0; c < 8; c += 2) {
        load_achunk(Aggh, Aggl, (c + 1) * 16 + kbase, bufB);
        mma_chunk(bufA, c);
        if (c + 2 < 8) load_achunk(Aggh, Aggl, (c + 2) * 16 + kbase, bufA);
        else           load_achunk(Hh, Hl, kbase, bufA);      // preload h half
        mma_chunk(bufB, c + 1);
    }
    // ---- group 1: h half (global chunks 8..15) ----
#pragma unroll 1
    for (int c = 0; c < 8; c += 2) {
        load_achunk(Hh, Hl, (c + 1) * 16 + kbase, bufB);
        mma_chunk(bufA, 8 + c);
        if (c + 2 < 8) load_achunk(Hh, Hl, (c + 2) * 16 + kbase, bufA);
        mma_chunk(bufB, 8 + c + 1);
    }

    // ---- epilogue in two 64-row halves through smem ----
    float4 bia = *(const float4*)(bl + lane * 4);
    float4 gm  = *(const float4*)(gamma + lane * 4);
    float4 bt  = *(const float4*)(beta + lane * 4);

    for (int half = 0; half < 2; half++) {
        __syncthreads();   // C free (or initial)
#pragma unroll
        for (int j = 0; j < 8; j++) {
            int c = nbase + j * 8 + 2 * tg;
            int r0 = mbase + gq;
            C[r0][c]     = acc[half][j][0];
            C[r0][c + 1] = acc[half][j][1];
            C[r0 + 8][c]     = acc[half][j][2];
            C[r0 + 8][c + 1] = acc[half][j][3];
        }
        __syncthreads();

        // warp w handles rows w*8..w*8+7 of this half
        for (int rr = 0; rr < 8; rr++) {
            int row = w * 8 + rr;
            int node = base + half * 64 + row;
            if (node >= N_NODES) continue;
            float4 v = *(float4*)&C[row][lane * 4];
            v.x += bia.x; v.y += bia.y; v.z += bia.z; v.w += bia.w;
            v.x = (v.x > 0.f) ? v.x : expm1f(v.x);
            v.y = (v.y > 0.f) ? v.y : expm1f(v.y);
            v.z = (v.z > 0.f) ? v.z : expm1f(v.z);
            v.w = (v.w > 0.f) ? v.w : expm1f(v.w);
            float s = v.x + v.y + v.z + v.w;
            float q = v.x * v.x + v.y * v.y + v.z * v.z + v.w * v.w;
#pragma unroll
            for (int o = 16; o > 0; o >>= 1) {
                s += __shfl_xor_sync(0xffffffffu, s, o);
                q += __shfl_xor_sync(0xffffffffu, q, o);
            }
            const float invH = 1.0f / HIDDEN;
            float mu = s * invH;
            float var = fmaxf(q * invH - mu * mu, 0.f);
            float rstd = rsqrtf(var + 1e-5f);
            float4 o4;
            o4.x = (v.x - mu) * rstd * gm.x + bt.x;
            o4.y = (v.y - mu) * rstd * gm.y + bt.y;
            o4.z = (v.z - mu) * rstd * gm.z + bt.z;
            o4.w = (v.w - mu) * rstd * gm.w + bt.w;
            long long ofs = (long long)node * HIDDEN + lane * 4;
            *(float4*)(h + ofs) = o4;
            __nv_bfloat16 h0, l0, h1, l1, h2, l2, h3, l3;
            split_bf(o4.x, h0, l0);
            split_bf(o4.y, h1, l1);
            split_bf(o4.z, h2, l2);
            split_bf(o4.w, h3, l3);
            *(uint2*)(Hh + ofs) = make_uint2(pack_bf2(h0, h1), pack_bf2(h2, h3));
            *(uint2*)(Hl + ofs) = make_uint2(pack_bf2(l0, l1), pack_bf2(l2, l3));
            if (do_pool) {
                int g = __ldg(&batch[node]);
                red_add_v4(pooled + (long long)g * HIDDEN + lane * 4, o4);
            }
        }
    }
}

// ---------------- head: pooled mean + two GEMVs ----------------
__global__ void head_kernel(const float* __restrict__ pooled, const float* __restrict__ cnt,
                            const float* __restrict__ Wm, const float* __restrict__ bm,
                            const float* __restrict__ Wt, const float* __restrict__ bt,
                            float* __restrict__ out)
{
    int g = blockIdx.x * blockDim.x + threadIdx.x;
    if (g >= N_GRAPHS) return;
    float inv = 1.0f / fmaxf(cnt[g], 1.0f);
    float s1 = 0.f, s2 = 0.f;
#pragma unroll 4
    for (int j = 0; j < HIDDEN; j++) {
        float p = pooled[g * HIDDEN + j];
        s1 += p * Wm[j];
        s2 += p * Wt[j];
    }
    out[g] = s1 * inv + bm[0];
    out[N_GRAPHS + g] = s2 * inv + bt[0];
}

// ---------------- launch ----------------
extern "C" void kernel_launch(void* const* d_in, const int* in_sizes, int n_in,
                              void* d_out, int out_size)
{
    const float* x      = (const float*)d_in[0];
    const int*   edge   = (const int*)d_in[1];
    const int*   batch  = (const int*)d_in[2];
    const float* W_op   = (const float*)d_in[3];
    const float* b_op   = (const float*)d_in[4];
    const float* W_l    = (const float*)d_in[5];
    const float* b_l    = (const float*)d_in[6];
    const float* W_r    = (const float*)d_in[7];
    const float* gamma  = (const float*)d_in[8];
    const float* beta   = (const float*)d_in[9];
    const float* W_mem  = (const float*)d_in[10];
    const float* b_mem  = (const float*)d_in[11];
    const float* W_time = (const float*)d_in[12];
    const float* b_time = (const float*)d_in[13];
    float* out = (float*)d_out;

    const int* src = edge;
    const int* dst = edge + N_EDGES;

    float *p_h, *p_cnt, *p_pool;
    __nv_bfloat16 *p_hh, *p_hl, *p_ah, *p_al;
    uint2 *p_wfrag;
    int *p_degi, *p_rowptr, *p_cursor, *p_ssrc, *p_bsum;
    cudaGetSymbolAddress((void**)&p_h, g_h);
    cudaGetSymbolAddress((void**)&p_hh, g_hh);
    cudaGetSymbolAddress((void**)&p_hl, g_hl);
    cudaGetSymbolAddress((void**)&p_ah, g_ah);
    cudaGetSymbolAddress((void**)&p_al, g_al);
    cudaGetSymbolAddress((void**)&p_wfrag, g_wfrag);
    cudaGetSymbolAddress((void**)&p_cnt, g_cnt);
    cudaGetSymbolAddress((void**)&p_pool, g_pool);
    cudaGetSymbolAddress((void**)&p_degi, g_degi);
    cudaGetSymbolAddress((void**)&p_rowptr, g_rowptr);
    cudaGetSymbolAddress((void**)&p_cursor, g_cursor);
    cudaGetSymbolAddress((void**)&p_ssrc, g_ssrc);
    cudaGetSymbolAddress((void**)&p_bsum, g_bsum);

    // 1: zero accumulated state
    zero_kernel<<<256, 256>>>(p_degi, p_cnt, p_pool);

    // 2: pre-split weights into b-fragment layout (once per launch)
    wsplit_kernel<<<64, 256>>>(W_l, W_r, p_wfrag);

    // 3: input projection (+ bf16 split) + degree histogram + batch count
    proj_hist_kernel<<<(N_NODES + PROJ_NPB - 1) / PROJ_NPB, 128>>>(
        x, W_op, b_op, p_h, p_hh, p_hl, dst, p_degi, batch, p_cnt);

    // 4-6: hierarchical scan (no spins)
    scan_local<<<SCAN_NB, SCAN_T>>>(p_degi, p_rowptr, p_bsum);
    scan_bsum<<<1, 32>>>(p_bsum);
    scan_add<<<(N_NODES + 255) / 256, 256>>>(p_rowptr, p_bsum, p_cursor);

    // 7: bucket edges at full parallelism
    bucket_kernel<<<(N_EDGES + 255) / 256, 256>>>(src, dst, p_cursor, p_ssrc);

    // 8..11: two layers of aggregate + tensor-core update
    for (int layer = 0; layer < 2; layer++) {
        aggregate_kernel<<<(N_NODES + 7) / 8, 256>>>(p_rowptr, p_ssrc, p_h, p_ah, p_al);
        update_mma_kernel<<<(N_NODES + UBM - 1) / UBM, 256>>>(
            p_ah, p_al, p_hh, p_hl, p_h, p_wfrag,
            b_l, gamma, beta, batch, p_pool, layer == 1);
    }

    // 12: head
    head_kernel<<<1, 256>>>(p_pool, p_cnt, W_mem, b_mem, W_time, b_time, out);
}

// round 15
// speedup vs baseline: 1.4803x; 1.4803x over previous
#include <cuda_runtime.h>
#include <cuda_bf16.h>

#define N_NODES  100000
#define N_EDGES  1600000
#define N_FEAT   32
#define HIDDEN   128
#define N_GRAPHS 256

#define SCAN_T   1024
#define SCAN_NB  98          // ceil(100000/1024)

#define UBM 128              // update kernel M-tile (nodes per block)
#define NPAD (N_NODES + UBM) // zero-padded rows for tail block

// ---------------- scratch (static device globals; no allocation) ----------------
__device__ float         g_h [NPAD * HIDDEN];   // fp32 h, natural layout (aggregate gathers this)
__device__ __nv_bfloat16 g_hh[NPAD * HIDDEN];   // h hi (bf16)
__device__ __nv_bfloat16 g_hl[NPAD * HIDDEN];   // h lo (bf16)
__device__ __nv_bfloat16 g_ah[NPAD * HIDDEN];   // agg hi
__device__ __nv_bfloat16 g_al[NPAD * HIDDEN];   // agg lo
__device__ uint2 g_wfrag[16 * 16 * 2 * 32];     // [cc][j][hi/lo][lane] b-fragments, 128KB
__device__ int   g_degi[N_NODES];
__device__ int   g_rowptr[N_NODES + 1];
__device__ int   g_cursor[N_NODES];
__device__ int   g_ssrc[N_EDGES];               // 6.4 MB
__device__ int   g_bsum[SCAN_NB];
__device__ float g_cnt[N_GRAPHS];
__device__ float g_pool[N_GRAPHS * HIDDEN];

// ---------------- helpers ----------------
__device__ __forceinline__ void red_add_v4(float* addr, float4 v) {
    asm volatile("red.global.add.v4.f32 [%0], {%1, %2, %3, %4};"
                 :: "l"(addr), "f"(v.x), "f"(v.y), "f"(v.z), "f"(v.w)
                 : "memory");
}

__device__ __forceinline__ unsigned pack_bf2(__nv_bfloat16 a, __nv_bfloat16 b) {
    __nv_bfloat162 t;
    t.x = a; t.y = b;
    return *reinterpret_cast<unsigned*>(&t);
}

__device__ __forceinline__ void split_bf(float v, __nv_bfloat16& hi, __nv_bfloat16& lo) {
    hi = __float2bfloat16(v);
    lo = __float2bfloat16(v - __bfloat162float(hi));
}

__device__ __forceinline__ void mma16816(float* d, const unsigned* a, unsigned b0, unsigned b1) {
    asm volatile(
        "mma.sync.aligned.m16n8k16.row.col.f32.bf16.bf16.f32 "
        "{%0,%1,%2,%3}, {%4,%5,%6,%7}, {%8,%9}, {%0,%1,%2,%3};\n"
        : "+f"(d[0]), "+f"(d[1]), "+f"(d[2]), "+f"(d[3])
        : "r"(a[0]), "r"(a[1]), "r"(a[2]), "r"(a[3]), "r"(b0), "r"(b1));
}

// L2-only load (no L1 fill) — keeps L1 free for the wfrag table
__device__ __forceinline__ unsigned ldcg_u32(const void* p) {
    unsigned v;
    asm volatile("ld.global.cg.b32 %0, [%1];" : "=r"(v) : "l"(p));
    return v;
}

// ---------------- zero: degi, cnt, pool ----------------
__global__ void zero_kernel(int* __restrict__ degi, float* __restrict__ cnt,
                            float* __restrict__ pool)
{
    int i = blockIdx.x * blockDim.x + threadIdx.x;
    int stride = gridDim.x * blockDim.x;
    for (int j = i; j < N_NODES; j += stride) degi[j] = 0;
    for (int j = i; j < N_GRAPHS * HIDDEN; j += stride) pool[j] = 0.f;
    if (i < N_GRAPHS) cnt[i] = 0.f;
}

// ---------------- weight pre-split into b-fragment layout ----------------
__global__ void wsplit_kernel(const float* __restrict__ Wl, const float* __restrict__ Wr,
                              uint2* __restrict__ wfrag)
{
    int idx = blockIdx.x * 256 + threadIdx.x;      // 0..16383
    int lane = idx & 31;
    int p    = (idx >> 5) & 1;
    int j    = (idx >> 6) & 15;
    int cc   = idx >> 10;
    int gq = lane >> 2, tg = lane & 3;
    int n  = j * 8 + gq;
    int kb = cc * 16 + 2 * tg;

    int ks[4] = {kb, kb + 1, kb + 8, kb + 9};
    __nv_bfloat16 b[4];
#pragma unroll
    for (int i = 0; i < 4; i++) {
        int k = ks[i];
        float v = (k < 128) ? Wl[k * HIDDEN + n] : Wr[(k - 128) * HIDDEN + n];
        __nv_bfloat16 hi, lo;
        split_bf(v, hi, lo);
        b[i] = p ? lo : hi;
    }
    wfrag[idx] = make_uint2(pack_bf2(b[0], b[1]), pack_bf2(b[2], b[3]));
}

// ---------------- fused: proj (h = x @ W_op + b_op, + bf16 split) + hist + count ----------------
#define PROJ_NPB 64
__global__ __launch_bounds__(128) void proj_hist_kernel(
    const float* __restrict__ x, const float* __restrict__ W,
    const float* __restrict__ b, float* __restrict__ h,
    __nv_bfloat16* __restrict__ hh, __nv_bfloat16* __restrict__ hl,
    const int* __restrict__ dst, int* __restrict__ degi,
    const int* __restrict__ batch, float* __restrict__ cnt)
{
    __shared__ __align__(16) float xs[PROJ_NPB][N_FEAT];  // 8 KB
    int j = threadIdx.x;
    int base = blockIdx.x * PROJ_NPB;

    float w[N_FEAT];
#pragma unroll
    for (int k = 0; k < N_FEAT; k++) w[k] = W[k * HIDDEN + j];
    float bj = b[j];

    for (int i = j; i < PROJ_NPB * N_FEAT; i += 128) {
        int m = i / N_FEAT, c = i % N_FEAT;
        int node = base + m;
        xs[m][c] = (node < N_NODES) ? x[(long long)node * N_FEAT + c] : 0.f;
    }
    __syncthreads();

    for (int m = 0; m < PROJ_NPB; m++) {
        int node = base + m;
        if (node >= N_NODES) break;
        float acc = bj;
#pragma unroll
        for (int k = 0; k < N_FEAT; k++) acc += xs[m][k] * w[k];
        long long ofs = (long long)node * HIDDEN + j;
        h[ofs] = acc;
        __nv_bfloat16 hi, lo;
        split_bf(acc, hi, lo);
        hh[ofs] = hi;
        hl[ofs] = lo;
    }

    // histogram + batch count (grid-stride, independent of proj output)
    int gt = blockIdx.x * 128 + threadIdx.x;
    int stride = gridDim.x * 128;
    for (int e = gt; e < N_EDGES; e += stride) atomicAdd(&degi[dst[e]], 1);
    for (int i2 = gt; i2 < N_NODES; i2 += stride) atomicAdd(&cnt[batch[i2]], 1.0f);
}

// ---------------- hierarchical scan: degi -> rowptr (exclusive) ----------------
__global__ __launch_bounds__(SCAN_T) void scan_local(
    const int* __restrict__ degi, int* __restrict__ rowptr, int* __restrict__ bsum)
{
    __shared__ int sm[SCAN_T];
    int t = threadIdx.x;
    int i = blockIdx.x * SCAN_T + t;
    int v = (i < N_NODES) ? degi[i] : 0;
    sm[t] = v;
    __syncthreads();
#pragma unroll
    for (int off = 1; off < SCAN_T; off <<= 1) {
        int add = (t >= off) ? sm[t - off] : 0;
        __syncthreads();
        sm[t] += add;
        __syncthreads();
    }
    if (i < N_NODES) rowptr[i] = sm[t] - v;
    if (t == SCAN_T - 1) bsum[blockIdx.x] = sm[t];
}

__global__ void scan_bsum(int* __restrict__ bsum) {
    if (threadIdx.x == 0) {
        int acc = 0;
        for (int b = 0; b < SCAN_NB; b++) { int v = bsum[b]; bsum[b] = acc; acc += v; }
    }
}

__global__ void scan_add(int* __restrict__ rowptr, const int* __restrict__ bsum,
                         int* __restrict__ cursor)
{
    int i = blockIdx.x * blockDim.x + threadIdx.x;
    if (i < N_NODES) {
        int v = rowptr[i] + bsum[i / SCAN_T];
        rowptr[i] = v;
        cursor[i] = v;
    }
    if (i == 0) rowptr[N_NODES] = N_EDGES;
}

// ---------------- bucket edges by dst (full parallelism) ----------------
__global__ void bucket_kernel(const int* __restrict__ src, const int* __restrict__ dst,
                              int* __restrict__ cursor, int* __restrict__ ssrc)
{
    int i = blockIdx.x * blockDim.x + threadIdx.x;
    if (i < N_EDGES) {
        int d = dst[i];
        int pos = atomicAdd(&cursor[d], 1);
        ssrc[pos] = src[i];
    }
}

// ---------------- CSR aggregate: agg[n] = mean of h[neighbors(n)] -> bf16 hi/lo ----------------
__global__ __launch_bounds__(256) void aggregate_kernel(
    const int* __restrict__ rowptr, const int* __restrict__ ssrc,
    const float* __restrict__ h,
    __nv_bfloat16* __restrict__ ah, __nv_bfloat16* __restrict__ al)
{
    int node = blockIdx.x * 8 + (threadIdx.x >> 5);
    if (node >= N_NODES) return;
    int lane = threadIdx.x & 31;
    int beg = __ldg(&rowptr[node]);
    int end = __ldg(&rowptr[node + 1]);

    float4 acc = make_float4(0.f, 0.f, 0.f, 0.f);
    int e = beg;
    for (; e + 4 <= end; e += 4) {
        int s0 = __ldg(&ssrc[e + 0]);
        int s1 = __ldg(&ssrc[e + 1]);
        int s2 = __ldg(&ssrc[e + 2]);
        int s3 = __ldg(&ssrc[e + 3]);
        float4 v0 = *(const float4*)(h + (long long)s0 * HIDDEN + lane * 4);
        float4 v1 = *(const float4*)(h + (long long)s1 * HIDDEN + lane * 4);
        float4 v2 = *(const float4*)(h + (long long)s2 * HIDDEN + lane * 4);
        float4 v3 = *(const float4*)(h + (long long)s3 * HIDDEN + lane * 4);
        acc.x += (v0.x + v1.x) + (v2.x + v3.x);
        acc.y += (v0.y + v1.y) + (v2.y + v3.y);
        acc.z += (v0.z + v1.z) + (v2.z + v3.z);
        acc.w += (v0.w + v1.w) + (v2.w + v3.w);
    }
    for (; e < end; e++) {
        int s0 = __ldg(&ssrc[e]);
        float4 v0 = *(const float4*)(h + (long long)s0 * HIDDEN + lane * 4);
        acc.x += v0.x; acc.y += v0.y; acc.z += v0.z; acc.w += v0.w;
    }
    float invd = 1.0f / fmaxf((float)(end - beg), 1.0f);
    acc.x *= invd; acc.y *= invd; acc.z *= invd; acc.w *= invd;

    __nv_bfloat16 h0, l0, h1, l1, h2, l2, h3, l3;
    split_bf(acc.x, h0, l0);
    split_bf(acc.y, h1, l1);
    split_bf(acc.z, h2, l2);
    split_bf(acc.w, h3, l3);
    long long ofs = (long long)node * HIDDEN + lane * 4;
    *(uint2*)(ah + ofs) = make_uint2(pack_bf2(h0, h1), pack_bf2(h2, h3));
    *(uint2*)(al + ofs) = make_uint2(pack_bf2(l0, l1), pack_bf2(l2, l3));
}

// ---------------- tensor-core update: h = LN(elu([agg|h] @ [Wl;Wr] + bl)) ----------------
// 128 nodes x 128 cols per block, 256 threads (8 warps: 4 along M x 2 along N),
// each warp owns TWO 16-row m-tiles. 2 blocks/SM via launch_bounds(256,2).
// a-frag loads use ld.global.cg (L2-only) so the 128KB wfrag table stays
// L1-resident; w-frag loads then hit L1 (~39cyc) instead of L2 (~250cyc).
__global__ __launch_bounds__(256, 2) void update_mma_kernel(
    const __nv_bfloat16* __restrict__ Aggh, const __nv_bfloat16* __restrict__ Aggl,
    __nv_bfloat16* __restrict__ Hh, __nv_bfloat16* __restrict__ Hl,
    float* __restrict__ h, const uint2* __restrict__ wfrag,
    const float* __restrict__ bl, const float* __restrict__ gamma,
    const float* __restrict__ beta, const int* __restrict__ batch,
    float* __restrict__ pooled, int do_pool)
{
    __shared__ float C[64][132];                  // epilogue staging, one 64-row half at a time

    int tid  = threadIdx.x;
    int lane = tid & 31;
    int w    = tid >> 5;
    int wm = w & 3, wn = w >> 2;
    int mbase = wm * 16, nbase = wn * 64;
    int base = blockIdx.x * UBM;
    int gq = lane >> 2, tg = lane & 3;

    // 32-bit offsets (arrays are < 2^31 elements) to save registers
    unsigned rA = (unsigned)(base + mbase + gq) * HIDDEN;   // tile0 row 0
    unsigned rB = rA + 8 * HIDDEN;                          // tile0 row +8
    unsigned rC = rA + 64 * HIDDEN;                         // tile1 row 0
    unsigned rD = rA + 72 * HIDDEN;                         // tile1 row +8

    float acc[2][8][4];
#pragma unroll
    for (int t2 = 0; t2 < 2; t2++)
#pragma unroll
        for (int j = 0; j < 8; j++)
#pragma unroll
            for (int i = 0; i < 4; i++) acc[t2][j][i] = 0.f;

    // K = 256 = [agg(128) | h(128)] x [Wl; Wr], 16 chunks of 16
#pragma unroll 1
    for (int cc = 0; cc < 16; cc++) {
        const __nv_bfloat16* PH = (cc < 8) ? Aggh : Hh;
        const __nv_bfloat16* PL = (cc < 8) ? Aggl : Hl;
        unsigned kk = (cc & 7) * 16 + 2 * tg;

        // batch all a-frag loads, L2-only (no L1 pollution)
        unsigned a0h[4], a0l[4], a1h[4], a1l[4];
        a0h[0] = ldcg_u32(PH + rA + kk);
        a0h[1] = ldcg_u32(PH + rB + kk);
        a0h[2] = ldcg_u32(PH + rA + kk + 8);
        a0h[3] = ldcg_u32(PH + rB + kk + 8);
        a1h[0] = ldcg_u32(PH + rC + kk);
        a1h[1] = ldcg_u32(PH + rD + kk);
        a1h[2] = ldcg_u32(PH + rC + kk + 8);
        a1h[3] = ldcg_u32(PH + rD + kk + 8);
        a0l[0] = ldcg_u32(PL + rA + kk);
        a0l[1] = ldcg_u32(PL + rB + kk);
        a0l[2] = ldcg_u32(PL + rA + kk + 8);
        a0l[3] = ldcg_u32(PL + rB + kk + 8);
        a1l[0] = ldcg_u32(PL + rC + kk);
        a1l[1] = ldcg_u32(PL + rD + kk);
        a1l[2] = ldcg_u32(PL + rC + kk + 8);
        a1l[3] = ldcg_u32(PL + rD + kk + 8);

        const uint2* wf = wfrag + (cc * 16 + wn * 8) * 2 * 32 + lane;
        uint2 wreg[16];
#pragma unroll
        for (int jj = 0; jj < 8; jj++) {
            wreg[2 * jj]     = __ldg(wf + (jj * 2) * 32);
            wreg[2 * jj + 1] = __ldg(wf + (jj * 2 + 1) * 32);
        }

#pragma unroll
        for (int jj = 0; jj < 8; jj++) {
            uint2 bh = wreg[2 * jj];
            uint2 bb = wreg[2 * jj + 1];
            mma16816(acc[0][jj], a0h, bh.x, bh.y);
            mma16816(acc[0][jj], a0h, bb.x, bb.y);
            mma16816(acc[0][jj], a0l, bh.x, bh.y);
            mma16816(acc[1][jj], a1h, bh.x, bh.y);
            mma16816(acc[1][jj], a1h, bb.x, bb.y);
            mma16816(acc[1][jj], a1l, bh.x, bh.y);
        }
    }

    // ---- epilogue in two 64-row halves through smem ----
    float4 bia = *(const float4*)(bl + lane * 4);
    float4 gm  = *(const float4*)(gamma + lane * 4);
    float4 bt  = *(const float4*)(beta + lane * 4);

    for (int half = 0; half < 2; half++) {
        __syncthreads();   // C free (or initial)
#pragma unroll
        for (int j = 0; j < 8; j++) {
            int c = nbase + j * 8 + 2 * tg;
            int r0 = mbase + gq;
            C[r0][c]     = acc[half][j][0];
            C[r0][c + 1] = acc[half][j][1];
            C[r0 + 8][c]     = acc[half][j][2];
            C[r0 + 8][c + 1] = acc[half][j][3];
        }
        __syncthreads();

        // warp w handles rows w*8..w*8+7 of this half
        for (int rr = 0; rr < 8; rr++) {
            int row = w * 8 + rr;
            int node = base + half * 64 + row;
            if (node >= N_NODES) continue;
            float4 v = *(float4*)&C[row][lane * 4];
            v.x += bia.x; v.y += bia.y; v.z += bia.z; v.w += bia.w;
            v.x = (v.x > 0.f) ? v.x : expm1f(v.x);
            v.y = (v.y > 0.f) ? v.y : expm1f(v.y);
            v.z = (v.z > 0.f) ? v.z : expm1f(v.z);
            v.w = (v.w > 0.f) ? v.w : expm1f(v.w);
            float s = v.x + v.y + v.z + v.w;
            float q = v.x * v.x + v.y * v.y + v.z * v.z + v.w * v.w;
#pragma unroll
            for (int o = 16; o > 0; o >>= 1) {
                s += __shfl_xor_sync(0xffffffffu, s, o);
                q += __shfl_xor_sync(0xffffffffu, q, o);
            }
            const float invH = 1.0f / HIDDEN;
            float mu = s * invH;
            float var = fmaxf(q * invH - mu * mu, 0.f);
            float rstd = rsqrtf(var + 1e-5f);
            float4 o4;
            o4.x = (v.x - mu) * rstd * gm.x + bt.x;
            o4.y = (v.y - mu) * rstd * gm.y + bt.y;
            o4.z = (v.z - mu) * rstd * gm.z + bt.z;
            o4.w = (v.w - mu) * rstd * gm.w + bt.w;
            long long ofs = (long long)node * HIDDEN + lane * 4;
            // L2-only stores (no L1 pollution; keeps wfrag resident)
            asm volatile("st.global.cg.v4.f32 [%0], {%1, %2, %3, %4};"
                         :: "l"(h + ofs), "f"(o4.x), "f"(o4.y), "f"(o4.z), "f"(o4.w) : "memory");
            __nv_bfloat16 h0, l0, h1, l1, h2, l2, h3, l3;
            split_bf(o4.x, h0, l0);
            split_bf(o4.y, h1, l1);
            split_bf(o4.z, h2, l2);
            split_bf(o4.w, h3, l3);
            unsigned hh0 = pack_bf2(h0, h1), hh1 = pack_bf2(h2, h3);
            unsigned ll0 = pack_bf2(l0, l1), ll1 = pack_bf2(l2, l3);
            asm volatile("st.global.cg.v2.b32 [%0], {%1, %2};"
                         :: "l"(Hh + ofs), "r"(hh0), "r"(hh1) : "memory");
            asm volatile("st.global.cg.v2.b32 [%0], {%1, %2};"
                         :: "l"(Hl + ofs), "r"(ll0), "r"(ll1) : "memory");
            if (do_pool) {
                int g = __ldg(&batch[node]);
                red_add_v4(pooled + (long long)g * HIDDEN + lane * 4, o4);
            }
        }
    }
}

// ---------------- head: pooled mean + two GEMVs ----------------
__global__ void head_kernel(const float* __restrict__ pooled, const float* __restrict__ cnt,
                            const float* __restrict__ Wm, const float* __restrict__ bm,
                            const float* __restrict__ Wt, const float* __restrict__ bt,
                            float* __restrict__ out)
{
    int g = blockIdx.x * blockDim.x + threadIdx.x;
    if (g >= N_GRAPHS) return;
    float inv = 1.0f / fmaxf(cnt[g], 1.0f);
    float s1 = 0.f, s2 = 0.f;
#pragma unroll 4
    for (int j = 0; j < HIDDEN; j++) {
        float p = pooled[g * HIDDEN + j];
        s1 += p * Wm[j];
        s2 += p * Wt[j];
    }
    out[g] = s1 * inv + bm[0];
    out[N_GRAPHS + g] = s2 * inv + bt[0];
}

// ---------------- launch ----------------
extern "C" void kernel_launch(void* const* d_in, const int* in_sizes, int n_in,
                              void* d_out, int out_size)
{
    const float* x      = (const float*)d_in[0];
    const int*   edge   = (const int*)d_in[1];
    const int*   batch  = (const int*)d_in[2];
    const float* W_op   = (const float*)d_in[3];
    const float* b_op   = (const float*)d_in[4];
    const float* W_l    = (const float*)d_in[5];
    const float* b_l    = (const float*)d_in[6];
    const float* W_r    = (const float*)d_in[7];
    const float* gamma  = (const float*)d_in[8];
    const float* beta   = (const float*)d_in[9];
    const float* W_mem  = (const float*)d_in[10];
    const float* b_mem  = (const float*)d_in[11];
    const float* W_time = (const float*)d_in[12];
    const float* b_time = (const float*)d_in[13];
    float* out = (float*)d_out;

    const int* src = edge;
    const int* dst = edge + N_EDGES;

    float *p_h, *p_cnt, *p_pool;
    __nv_bfloat16 *p_hh, *p_hl, *p_ah, *p_al;
    uint2 *p_wfrag;
    int *p_degi, *p_rowptr, *p_cursor, *p_ssrc, *p_bsum;
    cudaGetSymbolAddress((void**)&p_h, g_h);
    cudaGetSymbolAddress((void**)&p_hh, g_hh);
    cudaGetSymbolAddress((void**)&p_hl, g_hl);
    cudaGetSymbolAddress((void**)&p_ah, g_ah);
    cudaGetSymbolAddress((void**)&p_al, g_al);
    cudaGetSymbolAddress((void**)&p_wfrag, g_wfrag);
    cudaGetSymbolAddress((void**)&p_cnt, g_cnt);
    cudaGetSymbolAddress((void**)&p_pool, g_pool);
    cudaGetSymbolAddress((void**)&p_degi, g_degi);
    cudaGetSymbolAddress((void**)&p_rowptr, g_rowptr);
    cudaGetSymbolAddress((void**)&p_cursor, g_cursor);
    cudaGetSymbolAddress((void**)&p_ssrc, g_ssrc);
    cudaGetSymbolAddress((void**)&p_bsum, g_bsum);

    // 1: zero accumulated state
    zero_kernel<<<256, 256>>>(p_degi, p_cnt, p_pool);

    // 2: pre-split weights into b-fragment layout (once per launch)
    wsplit_kernel<<<64, 256>>>(W_l, W_r, p_wfrag);

    // 3: input projection (+ bf16 split) + degree histogram + batch count
    proj_hist_kernel<<<(N_NODES + PROJ_NPB - 1) / PROJ_NPB, 128>>>(
        x, W_op, b_op, p_h, p_hh, p_hl, dst, p_degi, batch, p_cnt);

    // 4-6: hierarchical scan (no spins)
    scan_local<<<SCAN_NB, SCAN_T>>>(p_degi, p_rowptr, p_bsum);
    scan_bsum<<<1, 32>>>(p_bsum);
    scan_add<<<(N_NODES + 255) / 256, 256>>>(p_rowptr, p_bsum, p_cursor);

    // 7: bucket edges at full parallelism
    bucket_kernel<<<(N_EDGES + 255) / 256, 256>>>(src, dst, p_cursor, p_ssrc);

    // 8..11: two layers of aggregate + tensor-core update
    for (int layer = 0; layer < 2; layer++) {
        aggregate_kernel<<<(N_NODES + 7) / 8, 256>>>(p_rowptr, p_ssrc, p_h, p_ah, p_al);
        update_mma_kernel<<<(N_NODES + UBM - 1) / UBM, 256>>>(
            p_ah, p_al, p_hh, p_hl, p_h, p_wfrag,
            b_l, gamma, beta, batch, p_pool, layer == 1);
    }

    // 12: head
    head_kernel<<<1, 256>>>(p_pool, p_cnt, W_mem, b_mem, W_time, b_time, out);
}

// round 17
// speedup vs baseline: 1.5440x; 1.0431x over previous
#include <cuda_runtime.h>
#include <cuda_bf16.h>

#define N_NODES  100000
#define N_EDGES  1600000
#define N_FEAT   32
#define HIDDEN   128
#define N_GRAPHS 256

#define SCAN_T   1024
#define SCAN_NB  98          // ceil(100000/1024)

#define UBM 128              // update kernel M-tile (nodes per block)
#define NPAD (N_NODES + UBM) // zero-padded rows for tail block

// ---------------- scratch (static device globals; no allocation) ----------------
__device__ float         g_h [NPAD * HIDDEN];   // fp32 h, natural layout (aggregate gathers this)
__device__ __nv_bfloat16 g_hh[NPAD * HIDDEN];   // h hi (bf16)
__device__ __nv_bfloat16 g_hl[NPAD * HIDDEN];   // h lo (bf16)
__device__ __nv_bfloat16 g_ah[NPAD * HIDDEN];   // agg hi
__device__ __nv_bfloat16 g_al[NPAD * HIDDEN];   // agg lo
__device__ uint2 g_wfrag[16 * 16 * 2 * 32];     // [cc][j][hi/lo][lane] b-fragments, 128KB
__device__ int   g_degi[N_NODES];
__device__ int   g_rowptr[N_NODES + 1];
__device__ int   g_cursor[N_NODES];
__device__ int   g_ssrc[N_EDGES];               // 6.4 MB
__device__ int   g_bsum[SCAN_NB];
__device__ float g_cnt[N_GRAPHS];
__device__ float g_pool[N_GRAPHS * HIDDEN];

// ---------------- helpers ----------------
__device__ __forceinline__ void red_add_v4(float* addr, float4 v) {
    asm volatile("red.global.add.v4.f32 [%0], {%1, %2, %3, %4};"
                 :: "l"(addr), "f"(v.x), "f"(v.y), "f"(v.z), "f"(v.w)
                 : "memory");
}

__device__ __forceinline__ unsigned pack_bf2(__nv_bfloat16 a, __nv_bfloat16 b) {
    __nv_bfloat162 t;
    t.x = a; t.y = b;
    return *reinterpret_cast<unsigned*>(&t);
}

__device__ __forceinline__ void split_bf(float v, __nv_bfloat16& hi, __nv_bfloat16& lo) {
    hi = __float2bfloat16(v);
    lo = __float2bfloat16(v - __bfloat162float(hi));
}

__device__ __forceinline__ void mma16816(float* d, const unsigned* a, unsigned b0, unsigned b1) {
    asm volatile(
        "mma.sync.aligned.m16n8k16.row.col.f32.bf16.bf16.f32 "
        "{%0,%1,%2,%3}, {%4,%5,%6,%7}, {%8,%9}, {%0,%1,%2,%3};\n"
        : "+f"(d[0]), "+f"(d[1]), "+f"(d[2]), "+f"(d[3])
        : "r"(a[0]), "r"(a[1]), "r"(a[2]), "r"(a[3]), "r"(b0), "r"(b1));
}

__device__ __forceinline__ void cp_async16(unsigned dst, const void* src) {
    asm volatile("cp.async.cg.shared.global [%0], [%1], 16;" :: "r"(dst), "l"(src));
}
__device__ __forceinline__ void cp_commit() {
    asm volatile("cp.async.commit_group;" ::: "memory");
}
template <int N>
__device__ __forceinline__ void cp_wait() {
    asm volatile("cp.async.wait_group %0;" :: "n"(N) : "memory");
}

__device__ __forceinline__ void ldsm4(unsigned* r, unsigned addr) {
    asm volatile("ldmatrix.sync.aligned.m8n8.x4.shared.b16 {%0,%1,%2,%3}, [%4];"
                 : "=r"(r[0]), "=r"(r[1]), "=r"(r[2]), "=r"(r[3]) : "r"(addr));
}

// ---------------- zero: degi, cnt, pool ----------------
__global__ void zero_kernel(int* __restrict__ degi, float* __restrict__ cnt,
                            float* __restrict__ pool)
{
    int i = blockIdx.x * blockDim.x + threadIdx.x;
    int stride = gridDim.x * blockDim.x;
    for (int j = i; j < N_NODES; j += stride) degi[j] = 0;
    for (int j = i; j < N_GRAPHS * HIDDEN; j += stride) pool[j] = 0.f;
    if (i < N_GRAPHS) cnt[i] = 0.f;
}

// ---------------- weight pre-split into b-fragment layout ----------------
__global__ void wsplit_kernel(const float* __restrict__ Wl, const float* __restrict__ Wr,
                              uint2* __restrict__ wfrag)
{
    int idx = blockIdx.x * 256 + threadIdx.x;      // 0..16383
    int lane = idx & 31;
    int p    = (idx >> 5) & 1;
    int j    = (idx >> 6) & 15;
    int cc   = idx >> 10;
    int gq = lane >> 2, tg = lane & 3;
    int n  = j * 8 + gq;
    int kb = cc * 16 + 2 * tg;

    int ks[4] = {kb, kb + 1, kb + 8, kb + 9};
    __nv_bfloat16 b[4];
#pragma unroll
    for (int i = 0; i < 4; i++) {
        int k = ks[i];
        float v = (k < 128) ? Wl[k * HIDDEN + n] : Wr[(k - 128) * HIDDEN + n];
        __nv_bfloat16 hi, lo;
        split_bf(v, hi, lo);
        b[i] = p ? lo : hi;
    }
    wfrag[idx] = make_uint2(pack_bf2(b[0], b[1]), pack_bf2(b[2], b[3]));
}

// ---------------- fused: proj (h = x @ W_op + b_op, + bf16 split) + hist + count ----------------
#define PROJ_NPB 64
__global__ __launch_bounds__(128) void proj_hist_kernel(
    const float* __restrict__ x, const float* __restrict__ W,
    const float* __restrict__ b, float* __restrict__ h,
    __nv_bfloat16* __restrict__ hh, __nv_bfloat16* __restrict__ hl,
    const int* __restrict__ dst, int* __restrict__ degi,
    const int* __restrict__ batch, float* __restrict__ cnt)
{
    __shared__ __align__(16) float xs[PROJ_NPB][N_FEAT];  // 8 KB
    int j = threadIdx.x;
    int base = blockIdx.x * PROJ_NPB;

    float w[N_FEAT];
#pragma unroll
    for (int k = 0; k < N_FEAT; k++) w[k] = W[k * HIDDEN + j];
    float bj = b[j];

    for (int i = j; i < PROJ_NPB * N_FEAT; i += 128) {
        int m = i / N_FEAT, c = i % N_FEAT;
        int node = base + m;
        xs[m][c] = (node < N_NODES) ? x[(long long)node * N_FEAT + c] : 0.f;
    }
    __syncthreads();

    for (int m = 0; m < PROJ_NPB; m++) {
        int node = base + m;
        if (node >= N_NODES) break;
        float acc = bj;
#pragma unroll
        for (int k = 0; k < N_FEAT; k++) acc += xs[m][k] * w[k];
        long long ofs = (long long)node * HIDDEN + j;
        h[ofs] = acc;
        __nv_bfloat16 hi, lo;
        split_bf(acc, hi, lo);
        hh[ofs] = hi;
        hl[ofs] = lo;
    }

    // histogram + batch count (grid-stride, independent of proj output)
    int gt = blockIdx.x * 128 + threadIdx.x;
    int stride = gridDim.x * 128;
    for (int e = gt; e < N_EDGES; e += stride) atomicAdd(&degi[dst[e]], 1);
    for (int i2 = gt; i2 < N_NODES; i2 += stride) atomicAdd(&cnt[batch[i2]], 1.0f);
}

// ---------------- hierarchical scan: degi -> rowptr (exclusive) ----------------
__global__ __launch_bounds__(SCAN_T) void scan_local(
    const int* __restrict__ degi, int* __restrict__ rowptr, int* __restrict__ bsum)
{
    __shared__ int sm[SCAN_T];
    int t = threadIdx.x;
    int i = blockIdx.x * SCAN_T + t;
    int v = (i < N_NODES) ? degi[i] : 0;
    sm[t] = v;
    __syncthreads();
#pragma unroll
    for (int off = 1; off < SCAN_T; off <<= 1) {
        int add = (t >= off) ? sm[t - off] : 0;
        __syncthreads();
        sm[t] += add;
        __syncthreads();
    }
    if (i < N_NODES) rowptr[i] = sm[t] - v;
    if (t == SCAN_T - 1) bsum[blockIdx.x] = sm[t];
}

__global__ void scan_bsum(int* __restrict__ bsum) {
    if (threadIdx.x == 0) {
        int acc = 0;
        for (int b = 0; b < SCAN_NB; b++) { int v = bsum[b]; bsum[b] = acc; acc += v; }
    }
}

__global__ void scan_add(int* __restrict__ rowptr, const int* __restrict__ bsum,
                         int* __restrict__ cursor)
{
    int i = blockIdx.x * blockDim.x + threadIdx.x;
    if (i < N_NODES) {
        int v = rowptr[i] + bsum[i / SCAN_T];
        rowptr[i] = v;
        cursor[i] = v;
    }
    if (i == 0) rowptr[N_NODES] = N_EDGES;
}

// ---------------- bucket edges by dst (full parallelism) ----------------
__global__ void bucket_kernel(const int* __restrict__ src, const int* __restrict__ dst,
                              int* __restrict__ cursor, int* __restrict__ ssrc)
{
    int i = blockIdx.x * blockDim.x + threadIdx.x;
    if (i < N_EDGES) {
        int d = dst[i];
        int pos = atomicAdd(&cursor[d], 1);
        ssrc[pos] = src[i];
    }
}

// ---------------- CSR aggregate: agg[n] = mean of h[neighbors(n)] -> bf16 hi/lo ----------------
__global__ __launch_bounds__(256) void aggregate_kernel(
    const int* __restrict__ rowptr, const int* __restrict__ ssrc,
    const float* __restrict__ h,
    __nv_bfloat16* __restrict__ ah, __nv_bfloat16* __restrict__ al)
{
    int node = blockIdx.x * 8 + (threadIdx.x >> 5);
    if (node >= N_NODES) return;
    int lane = threadIdx.x & 31;
    int beg = __ldg(&rowptr[node]);
    int end = __ldg(&rowptr[node + 1]);

    float4 acc = make_float4(0.f, 0.f, 0.f, 0.f);
    int e = beg;
    for (; e + 4 <= end; e += 4) {
        int s0 = __ldg(&ssrc[e + 0]);
        int s1 = __ldg(&ssrc[e + 1]);
        int s2 = __ldg(&ssrc[e + 2]);
        int s3 = __ldg(&ssrc[e + 3]);
        float4 v0 = *(const float4*)(h + (long long)s0 * HIDDEN + lane * 4);
        float4 v1 = *(const float4*)(h + (long long)s1 * HIDDEN + lane * 4);
        float4 v2 = *(const float4*)(h + (long long)s2 * HIDDEN + lane * 4);
        float4 v3 = *(const float4*)(h + (long long)s3 * HIDDEN + lane * 4);
        acc.x += (v0.x + v1.x) + (v2.x + v3.x);
        acc.y += (v0.y + v1.y) + (v2.y + v3.y);
        acc.z += (v0.z + v1.z) + (v2.z + v3.z);
        acc.w += (v0.w + v1.w) + (v2.w + v3.w);
    }
    for (; e < end; e++) {
        int s0 = __ldg(&ssrc[e]);
        float4 v0 = *(const float4*)(h + (long long)s0 * HIDDEN + lane * 4);
        acc.x += v0.x; acc.y += v0.y; acc.z += v0.z; acc.w += v0.w;
    }
    float invd = 1.0f / fmaxf((float)(end - beg), 1.0f);
    acc.x *= invd; acc.y *= invd; acc.z *= invd; acc.w *= invd;

    __nv_bfloat16 h0, l0, h1, l1, h2, l2, h3, l3;
    split_bf(acc.x, h0, l0);
    split_bf(acc.y, h1, l1);
    split_bf(acc.z, h2, l2);
    split_bf(acc.w, h3, l3);
    long long ofs = (long long)node * HIDDEN + lane * 4;
    *(uint2*)(ah + ofs) = make_uint2(pack_bf2(h0, h1), pack_bf2(h2, h3));
    *(uint2*)(al + ofs) = make_uint2(pack_bf2(l0, l1), pack_bf2(l2, l3));
}

// ---------------- tensor-core update: h = LN(elu([agg|h] @ [Wl;Wr] + bl)) ----------------
// 128 nodes x 128 cols per block, 256 threads (8 warps: 4 along M x 2 along N),
// each warp owns TWO 16-row m-tiles. 2 blocks/SM via launch_bounds(256,2).
// A chunks staged to smem via double-buffered cp.async (coalesced 16B),
// consumed via ldmatrix.x4 — zero extra registers, latency absorbed async.
#define AROW 24                     // smem row stride in bf16 (48B, LDSM conflict-free)
#define ABUF (2 * 128 * AROW)       // one buffer (hi+lo), in bf16 elems
#define ALO  (128 * AROW)           // lo-plane offset within buffer, in bf16 elems
__global__ __launch_bounds__(256, 2) void update_mma_kernel(
    const __nv_bfloat16* __restrict__ Aggh, const __nv_bfloat16* __restrict__ Aggl,
    __nv_bfloat16* __restrict__ Hh, __nv_bfloat16* __restrict__ Hl,
    float* __restrict__ h, const uint2* __restrict__ wfrag,
    const float* __restrict__ bl, const float* __restrict__ gamma,
    const float* __restrict__ beta, const int* __restrict__ batch,
    float* __restrict__ pooled, int do_pool)
{
    __shared__ __align__(16) union {
        __nv_bfloat16 A[2][2][128][AROW];   // [buf][hi/lo][row][col] = 24KB
        float C[64][132];                   // epilogue staging = 34KB
    } u;

    int tid  = threadIdx.x;
    int lane = tid & 31;
    int w    = tid >> 5;
    int wm = w & 3, wn = w >> 2;
    int mbase = wm * 16, nbase = wn * 64;
    int base = blockIdx.x * UBM;
    int gq = lane >> 2, tg = lane & 3;

    unsigned sA = (unsigned)__cvta_generic_to_shared(&u);

    // staging: thread copies 16B of hi and 16B of lo per chunk (row = tid/2, half = tid&1)
    int srow = tid >> 1, shalf = tid & 1;
    unsigned sdst = sA + (unsigned)(srow * AROW + shalf * 8) * 2;       // bytes
    unsigned ssrc = (unsigned)(base + srow) * HIDDEN + shalf * 8;       // elems

    // ldsm: lane -> 8x8 tile (g8) and row within tile (r8)
    int g8 = lane >> 3, r8 = lane & 7;
    unsigned ldsm_off = (unsigned)((mbase + ((g8 & 1) << 3) + r8) * AROW * 2 + ((g8 >> 1) << 4));

    float acc[2][8][4];
#pragma unroll
    for (int t2 = 0; t2 < 2; t2++)
#pragma unroll
        for (int j = 0; j < 8; j++)
#pragma unroll
            for (int i = 0; i < 4; i++) acc[t2][j][i] = 0.f;

    // prologue: stage chunks 0 and 1
    {
        cp_async16(sdst,               Aggh + ssrc);
        cp_async16(sdst + ALO * 2,     Aggl + ssrc);
        cp_commit();
        cp_async16(sdst + ABUF * 2,           Aggh + ssrc + 16);
        cp_async16(sdst + ABUF * 2 + ALO * 2, Aggl + ssrc + 16);
        cp_commit();
    }

    // K = 256 = [agg(128) | h(128)] x [Wl; Wr], 16 chunks of 16
#pragma unroll 1
    for (int cc = 0; cc < 16; cc++) {
        if (cc < 15) cp_wait<1>(); else cp_wait<0>();
        __syncthreads();

        // a-frags via 4x ldmatrix.x4 from the current buffer
        unsigned abase = sA + (unsigned)((cc & 1) * ABUF * 2) + ldsm_off;
        unsigned a0h[4], a1h[4], a0l[4], a1l[4];
        ldsm4(a0h, abase);
        ldsm4(a1h, abase + 64 * AROW * 2);
        ldsm4(a0l, abase + ALO * 2);
        ldsm4(a1l, abase + ALO * 2 + 64 * AROW * 2);

        const uint2* wf = wfrag + (cc * 16 + wn * 8) * 2 * 32 + lane;
        uint2 wreg[16];
#pragma unroll
        for (int jj = 0; jj < 8; jj++) {
            wreg[2 * jj]     = __ldg(wf + (jj * 2) * 32);
            wreg[2 * jj + 1] = __ldg(wf + (jj * 2 + 1) * 32);
        }

#pragma unroll
        for (int jj = 0; jj < 8; jj++) {
            uint2 bh = wreg[2 * jj];
            uint2 bb = wreg[2 * jj + 1];
            mma16816(acc[0][jj], a0h, bh.x, bh.y);
            mma16816(acc[0][jj], a0h, bb.x, bb.y);
            mma16816(acc[0][jj], a0l, bh.x, bh.y);
            mma16816(acc[1][jj], a1h, bh.x, bh.y);
            mma16816(acc[1][jj], a1h, bb.x, bb.y);
            mma16816(acc[1][jj], a1l, bh.x, bh.y);
        }
        __syncthreads();   // all consumers done with buf (cc&1) before restaging it

        int nc = cc + 2;
        if (nc < 16) {
            const __nv_bfloat16* PH = (nc < 8) ? Aggh : Hh;
            const __nv_bfloat16* PL = (nc < 8) ? Aggl : Hl;
            unsigned ko = (unsigned)((nc & 7) * 16);
            unsigned d = sdst + (unsigned)((nc & 1) * ABUF * 2);
            cp_async16(d,           PH + ssrc + ko);
            cp_async16(d + ALO * 2, PL + ssrc + ko);
            cp_commit();
        }
    }

    // ---- epilogue in two 64-row halves through smem ----
    float4 bia = *(const float4*)(bl + lane * 4);
    float4 gm  = *(const float4*)(gamma + lane * 4);
    float4 bt  = *(const float4*)(beta + lane * 4);

    for (int half = 0; half < 2; half++) {
        __syncthreads();   // C free (or initial; mainloop fully drained)
#pragma unroll
        for (int j = 0; j < 8; j++) {
            int c = nbase + j * 8 + 2 * tg;
            int r0 = mbase + gq;
            u.C[r0][c]     = acc[half][j][0];
            u.C[r0][c + 1] = acc[half][j][1];
            u.C[r0 + 8][c]     = acc[half][j][2];
            u.C[r0 + 8][c + 1] = acc[half][j][3];
        }
        __syncthreads();

        // warp w handles rows w*8..w*8+7 of this half
        for (int rr = 0; rr < 8; rr++) {
            int row = w * 8 + rr;
            int node = base + half * 64 + row;
            if (node >= N_NODES) continue;
            float4 v = *(float4*)&u.C[row][lane * 4];
            v.x += bia.x; v.y += bia.y; v.z += bia.z; v.w += bia.w;
            v.x = (v.x > 0.f) ? v.x : expm1f(v.x);
            v.y = (v.y > 0.f) ? v.y : expm1f(v.y);
            v.z = (v.z > 0.f) ? v.z : expm1f(v.z);
            v.w = (v.w > 0.f) ? v.w : expm1f(v.w);
            float s = v.x + v.y + v.z + v.w;
            float q = v.x * v.x + v.y * v.y + v.z * v.z + v.w * v.w;
#pragma unroll
            for (int o = 16; o > 0; o >>= 1) {
                s += __shfl_xor_sync(0xffffffffu, s, o);
                q += __shfl_xor_sync(0xffffffffu, q, o);
            }
            const float invH = 1.0f / HIDDEN;
            float mu = s * invH;
            float var = fmaxf(q * invH - mu * mu, 0.f);
            float rstd = rsqrtf(var + 1e-5f);
            float4 o4;
            o4.x = (v.x - mu) * rstd * gm.x + bt.x;
            o4.y = (v.y - mu) * rstd * gm.y + bt.y;
            o4.z = (v.z - mu) * rstd * gm.z + bt.z;
            o4.w = (v.w - mu) * rstd * gm.w + bt.w;
            long long ofs = (long long)node * HIDDEN + lane * 4;
            *(float4*)(h + ofs) = o4;
            __nv_bfloat16 h0, l0, h1, l1, h2, l2, h3, l3;
            split_bf(o4.x, h0, l0);
            split_bf(o4.y, h1, l1);
            split_bf(o4.z, h2, l2);
            split_bf(o4.w, h3, l3);
            *(uint2*)(Hh + ofs) = make_uint2(pack_bf2(h0, h1), pack_bf2(h2, h3));
            *(uint2*)(Hl + ofs) = make_uint2(pack_bf2(l0, l1), pack_bf2(l2, l3));
            if (do_pool) {
                int g = __ldg(&batch[node]);
                red_add_v4(pooled + (long long)g * HIDDEN + lane * 4, o4);
            }
        }
    }
}

// ---------------- head: pooled mean + two GEMVs ----------------
__global__ void head_kernel(const float* __restrict__ pooled, const float* __restrict__ cnt,
                            const float* __restrict__ Wm, const float* __restrict__ bm,
                            const float* __restrict__ Wt, const float* __restrict__ bt,
                            float* __restrict__ out)
{
    int g = blockIdx.x * blockDim.x + threadIdx.x;
    if (g >= N_GRAPHS) return;
    float inv = 1.0f / fmaxf(cnt[g], 1.0f);
    float s1 = 0.f, s2 = 0.f;
#pragma unroll 4
    for (int j = 0; j < HIDDEN; j++) {
        float p = pooled[g * HIDDEN + j];
        s1 += p * Wm[j];
        s2 += p * Wt[j];
    }
    out[g] = s1 * inv + bm[0];
    out[N_GRAPHS + g] = s2 * inv + bt[0];
}

// ---------------- launch ----------------
extern "C" void kernel_launch(void* const* d_in, const int* in_sizes, int n_in,
                              void* d_out, int out_size)
{
    const float* x      = (const float*)d_in[0];
    const int*   edge   = (const int*)d_in[1];
    const int*   batch  = (const int*)d_in[2];
    const float* W_op   = (const float*)d_in[3];
    const float* b_op   = (const float*)d_in[4];
    const float* W_l    = (const float*)d_in[5];
    const float* b_l    = (const float*)d_in[6];
    const float* W_r    = (const float*)d_in[7];
    const float* gamma  = (const float*)d_in[8];
    const float* beta   = (const float*)d_in[9];
    const float* W_mem  = (const float*)d_in[10];
    const float* b_mem  = (const float*)d_in[11];
    const float* W_time = (const float*)d_in[12];
    const float* b_time = (const float*)d_in[13];
    float* out = (float*)d_out;

    const int* src = edge;
    const int* dst = edge + N_EDGES;

    float *p_h, *p_cnt, *p_pool;
    __nv_bfloat16 *p_hh, *p_hl, *p_ah, *p_al;
    uint2 *p_wfrag;
    int *p_degi, *p_rowptr, *p_cursor, *p_ssrc, *p_bsum;
    cudaGetSymbolAddress((void**)&p_h, g_h);
    cudaGetSymbolAddress((void**)&p_hh, g_hh);
    cudaGetSymbolAddress((void**)&p_hl, g_hl);
    cudaGetSymbolAddress((void**)&p_ah, g_ah);
    cudaGetSymbolAddress((void**)&p_al, g_al);
    cudaGetSymbolAddress((void**)&p_wfrag, g_wfrag);
    cudaGetSymbolAddress((void**)&p_cnt, g_cnt);
    cudaGetSymbolAddress((void**)&p_pool, g_pool);
    cudaGetSymbolAddress((void**)&p_degi, g_degi);
    cudaGetSymbolAddress((void**)&p_rowptr, g_rowptr);
    cudaGetSymbolAddress((void**)&p_cursor, g_cursor);
    cudaGetSymbolAddress((void**)&p_ssrc, g_ssrc);
    cudaGetSymbolAddress((void**)&p_bsum, g_bsum);

    // 1: zero accumulated state
    zero_kernel<<<256, 256>>>(p_degi, p_cnt, p_pool);

    // 2: pre-split weights into b-fragment layout (once per launch)
    wsplit_kernel<<<64, 256>>>(W_l, W_r, p_wfrag);

    // 3: input projection (+ bf16 split) + degree histogram + batch count
    proj_hist_kernel<<<(N_NODES + PROJ_NPB - 1) / PROJ_NPB, 128>>>(
        x, W_op, b_op, p_h, p_hh, p_hl, dst, p_degi, batch, p_cnt);

    // 4-6: hierarchical scan (no spins)
    scan_local<<<SCAN_NB, SCAN_T>>>(p_degi, p_rowptr, p_bsum);
    scan_bsum<<<1, 32>>>(p_bsum);
    scan_add<<<(N_NODES + 255) / 256, 256>>>(p_rowptr, p_bsum, p_cursor);

    // 7: bucket edges at full parallelism
    bucket_kernel<<<(N_EDGES + 255) / 256, 256>>>(src, dst, p_cursor, p_ssrc);

    // 8..11: two layers of aggregate + tensor-core update
    for (int layer = 0; layer < 2; layer++) {
        aggregate_kernel<<<(N_NODES + 7) / 8, 256>>>(p_rowptr, p_ssrc, p_h, p_ah, p_al);
        update_mma_kernel<<<(N_NODES + UBM - 1) / UBM, 256>>>(
            p_ah, p_al, p_hh, p_hl, p_h, p_wfrag,
            b_l, gamma, beta, batch, p_pool, layer == 1);
    }

    // 12: head
    head_kernel<<<1, 256>>>(p_pool, p_cnt, W_mem, b_mem, W_time, b_time, out);
}